// round 7
// baseline (speedup 1.0000x reference)
#include <cuda_runtime.h>
#include <cuda_fp16.h>
#include <cstdint>

#define NUM_T 64
#define DIN   4096
#define DOUT  11008
#define KS    4
#define KPER  (DIN / KS)     // 1024
#define KC    64
#define NCHUNK (KPER / KC)   // 16
#define NT    64
#define SSTRIDE 72           // +8 half pad: row stride 144B, conflict-free ldmatrix
#define NSTAGE 4
#define STAGE_HALVES (2 * NUM_T * SSTRIDE)   // X tile + W tile, in halves
#define STAGE_B (STAGE_HALVES * 2)           // 18432 bytes
#define SMEM_TOTAL (NSTAGE * STAGE_B)        // 73728 bytes

// Scratch (allocation-free rule: __device__ globals)
__device__ __align__(256) __half g_xq[NUM_T * DIN];
__device__ __align__(256) float  g_part[KS * NUM_T * DOUT];   // 11.27 MB

// ---------------------------------------------------------------------------
// MXFP4 block constants from amax (integer bit-pattern construction)
// ---------------------------------------------------------------------------
__device__ __forceinline__ void mk_consts(float amax, float& c6s, float& cM,
                                          uint32_t& c2s_bits) {
    if (!(amax > 0.0f)) amax = 1.0f;
    int e  = ((__float_as_int(amax) >> 23) & 0xFF) - 127;
    int se = min(max(e - 2, -127), 127);
    c6s = __int_as_float(((se + 129) << 23) | 0x400000);   // 6 * 2^se
    cM  = __int_as_float((se + 149) << 23);                // 2^(se+22) magic
    c2s_bits = (uint32_t)((se + 128) << 23);               // bits of 2^(se+1)
}

// E2M1 qdq in the t-domain. Exactly matches reference (clip 6*scale, RNE on
// E2M1 grid incl. 0.5*scale subnormal step).
__device__ __forceinline__ float qdq_fast(float t, float c6s, float cM,
                                          uint32_t c2s_bits) {
    float a = fminf(fabsf(t), c6s);
    uint32_t u = __float_as_uint(a);
    uint32_t r1 = (u + 0x1FFFFFu + ((u >> 22) & 1u)) & 0xFFC00000u;
    float q2 = __fadd_rn(__fadd_rn(a, cM), -cM);
    uint32_t q = (u < c2s_bits) ? __float_as_uint(q2) : r1;
    return __uint_as_float(q | (__float_as_uint(t) & 0x80000000u));
}

// ---------------------------------------------------------------------------
// x quant-dequant -> f16 (one MXFP block = 8 lanes x float4)
// ---------------------------------------------------------------------------
__global__ void qdq_x_kernel(const float* __restrict__ in) {
    int gtid = blockIdx.x * blockDim.x + threadIdx.x;
    int warp = gtid >> 5;
    int lane = threadIdx.x & 31;
    long base = (long)warp * 128 + (long)lane * 4;
    if (base >= NUM_T * DIN) return;
    float4 v = *reinterpret_cast<const float4*>(in + base);
    float am = fmaxf(fmaxf(fabsf(v.x), fabsf(v.y)), fmaxf(fabsf(v.z), fabsf(v.w)));
    am = fmaxf(am, __shfl_xor_sync(0xffffffffu, am, 1));
    am = fmaxf(am, __shfl_xor_sync(0xffffffffu, am, 2));
    am = fmaxf(am, __shfl_xor_sync(0xffffffffu, am, 4));
    float c6s, cM; uint32_t c2sb;
    mk_consts(am, c6s, cM, c2sb);
    __half2 h0 = __floats2half2_rn(qdq_fast(v.x, c6s, cM, c2sb),
                                   qdq_fast(v.y, c6s, cM, c2sb));
    __half2 h1 = __floats2half2_rn(qdq_fast(v.z, c6s, cM, c2sb),
                                   qdq_fast(v.w, c6s, cM, c2sb));
    uint2 st;
    st.x = *reinterpret_cast<uint32_t*>(&h0);
    st.y = *reinterpret_cast<uint32_t*>(&h1);
    *reinterpret_cast<uint2*>(&g_xq[base]) = st;
}

// ---------------------------------------------------------------------------
// Warp-specialized fused GEMM: 8 producer warps (LDG + qdq + STS into 4-stage
// ring) / 4 consumer warps (ldmatrix + HMMA). Named barriers decouple them.
//   full[s]  (id 1+s): producers arrive, consumers sync   (count 384)
//   empty[s] (id 5+s): consumers arrive, producers sync   (count 384)
// ---------------------------------------------------------------------------
#define BAR_SYNC(id)   asm volatile("bar.sync %0, 384;"   :: "r"(id) : "memory")
#define BAR_ARRIVE(id) asm volatile("bar.arrive %0, 384;" :: "r"(id) : "memory")

#define LDMATRIX_X4(r0, r1, r2, r3, addr)                                        \
    asm volatile("ldmatrix.sync.aligned.m8n8.x4.shared.b16 {%0,%1,%2,%3}, [%4];" \
                 : "=r"(r0), "=r"(r1), "=r"(r2), "=r"(r3) : "r"(addr))

#define MMA16816(c, a0, a1, a2, a3, b0, b1)                                   \
    asm volatile("mma.sync.aligned.m16n8k16.row.col.f32.f16.f16.f32 "         \
                 "{%0,%1,%2,%3}, {%4,%5,%6,%7}, {%8,%9}, {%0,%1,%2,%3};"      \
                 : "+f"(c[0]), "+f"(c[1]), "+f"(c[2]), "+f"(c[3])             \
                 : "r"(a0), "r"(a1), "r"(a2), "r"(a3), "r"(b0), "r"(b1))

__global__ __launch_bounds__(384, 2) void fused_gemm_ws(const float* __restrict__ W) {
    extern __shared__ __half sm[];   // stage s: X at s*STAGE_HALVES, W at +NUM_T*SSTRIDE
    int tid = threadIdx.x;
    int nbase = blockIdx.x * NT;
    int kbase = blockIdx.y * KPER;

    if (tid < 256) {
        // ================= PRODUCERS (warps 0-7) =================
        int wrow = tid >> 2;
        int wk   = (tid & 3) << 4;          // 16 consecutive K floats (half a 32-block)
        const float* wp = W + (size_t)(nbase + wrow) * DIN + kbase + wk;
        int xr0 = tid >> 3, xc0 = (tid & 7) * 8;
        const __half* xp0 = &g_xq[xr0 * DIN + kbase + xc0];
        const __half* xp1 = xp0 + 32 * DIN;  // row xr0+32

        float4 wv[4];
        uint4 xv0, xv1;
        #pragma unroll
        for (int j = 0; j < 4; j++)
            wv[j] = reinterpret_cast<const float4*>(wp)[j];
        xv0 = *reinterpret_cast<const uint4*>(xp0);
        xv1 = *reinterpret_cast<const uint4*>(xp1);

        #pragma unroll 1
        for (int c = 0; c < NCHUNK; c++) {
            int s = c & 3;
            if (c >= NSTAGE) BAR_SYNC(5 + s);
            __half* Xs = sm + s * STAGE_HALVES;
            __half* Ws = Xs + NUM_T * SSTRIDE;
            *reinterpret_cast<uint4*>(&Xs[xr0 * SSTRIDE + xc0])        = xv0;
            *reinterpret_cast<uint4*>(&Xs[(xr0 + 32) * SSTRIDE + xc0]) = xv1;
            {   // quantize the 64 W floats this thread-pair's 32-blocks hold
                float am = 0.0f;
                #pragma unroll
                for (int j = 0; j < 4; j++)
                    am = fmaxf(am, fmaxf(fmaxf(fabsf(wv[j].x), fabsf(wv[j].y)),
                                         fmaxf(fabsf(wv[j].z), fabsf(wv[j].w))));
                am = fmaxf(am, __shfl_xor_sync(0xffffffffu, am, 1));  // 32-block amax
                float c6s, cM; uint32_t c2sb;
                mk_consts(am, c6s, cM, c2sb);
                uint32_t qq[8];
                #pragma unroll
                for (int j = 0; j < 4; j++) {
                    __half2 h0 = __floats2half2_rn(qdq_fast(wv[j].x, c6s, cM, c2sb),
                                                   qdq_fast(wv[j].y, c6s, cM, c2sb));
                    __half2 h1 = __floats2half2_rn(qdq_fast(wv[j].z, c6s, cM, c2sb),
                                                   qdq_fast(wv[j].w, c6s, cM, c2sb));
                    qq[2 * j]     = *reinterpret_cast<uint32_t*>(&h0);
                    qq[2 * j + 1] = *reinterpret_cast<uint32_t*>(&h1);
                }
                *reinterpret_cast<uint4*>(&Ws[wrow * SSTRIDE + wk])     =
                    make_uint4(qq[0], qq[1], qq[2], qq[3]);
                *reinterpret_cast<uint4*>(&Ws[wrow * SSTRIDE + wk + 8]) =
                    make_uint4(qq[4], qq[5], qq[6], qq[7]);
            }
            // prefetch next chunk (overlaps with the wait in next iteration)
            if (c + 1 < NCHUNK) {
                int kc = (c + 1) * KC;
                #pragma unroll
                for (int j = 0; j < 4; j++)
                    wv[j] = reinterpret_cast<const float4*>(wp + kc)[j];
                xv0 = *reinterpret_cast<const uint4*>(xp0 + kc);
                xv1 = *reinterpret_cast<const uint4*>(xp1 + kc);
            }
            asm volatile("membar.cta;" ::: "memory");   // drain STS before arrive
            BAR_ARRIVE(1 + s);
        }
    } else {
        // ================= CONSUMERS (warps 8-11) =================
        int w    = (tid >> 5) - 8;     // 0..3
        int lane = tid & 31;
        int mrow = w * 16;
        int q = lane >> 3, li = lane & 7;
        uint32_t a_base = (uint32_t)__cvta_generic_to_shared(
            &sm[(mrow + (q & 1) * 8 + li) * SSTRIDE + (q >> 1) * 8]);
        uint32_t b_base = (uint32_t)__cvta_generic_to_shared(
            &sm[NUM_T * SSTRIDE + ((q >> 1) * 8 + li) * SSTRIDE + (q & 1) * 8]);

        float acc[8][4];
        #pragma unroll
        for (int i = 0; i < 8; i++)
            #pragma unroll
            for (int j = 0; j < 4; j++) acc[i][j] = 0.0f;

        #pragma unroll 1
        for (int c = 0; c < NCHUNK; c++) {
            int s = c & 3;
            BAR_SYNC(1 + s);
            uint32_t off = (uint32_t)s * STAGE_B;
            #pragma unroll
            for (int ks = 0; ks < 4; ks++) {
                uint32_t a0, a1, a2, a3;
                LDMATRIX_X4(a0, a1, a2, a3, a_base + off + ks * 32);
                #pragma unroll
                for (int nb = 0; nb < 4; nb++) {
                    uint32_t b0, b1, b2, b3;
                    LDMATRIX_X4(b0, b1, b2, b3,
                                b_base + off + nb * (16 * SSTRIDE * 2) + ks * 32);
                    MMA16816(acc[2 * nb + 0], a0, a1, a2, a3, b0, b1);
                    MMA16816(acc[2 * nb + 1], a0, a1, a2, a3, b2, b3);
                }
            }
            BAR_ARRIVE(5 + s);   // reads done (HMMA issued => LDSM completed)
        }

        // epilogue: fp32 partials. Each warp: rows [mrow, mrow+16), all 64 cols.
        float* pb = g_part + (size_t)blockIdx.y * NUM_T * DOUT;
        int tg = lane >> 2, tig = lane & 3;
        #pragma unroll
        for (int nf = 0; nf < 8; nf++) {
            int col = nbase + nf * 8 + tig * 2;
            int r0  = mrow + tg;
            *reinterpret_cast<float2*>(&pb[(size_t)r0 * DOUT + col]) =
                make_float2(acc[nf][0], acc[nf][1]);
            *reinterpret_cast<float2*>(&pb[(size_t)(r0 + 8) * DOUT + col]) =
                make_float2(acc[nf][2], acc[nf][3]);
        }
    }
}

// ---------------------------------------------------------------------------
// Reduce K-splits + bias qdq. 1 thread = 1 float4 of output.
// ---------------------------------------------------------------------------
__global__ void reduce_bias_kernel(const float* __restrict__ bias, float* __restrict__ out) {
    int t  = blockIdx.x * blockDim.x + threadIdx.x;
    int m  = t / (DOUT / 4);
    int o  = (t % (DOUT / 4)) * 4;

    float4 b4 = *reinterpret_cast<const float4*>(bias + o);
    float am = fmaxf(fmaxf(fabsf(b4.x), fabsf(b4.y)), fmaxf(fabsf(b4.z), fabsf(b4.w)));
    am = fmaxf(am, __shfl_xor_sync(0xffffffffu, am, 1));
    am = fmaxf(am, __shfl_xor_sync(0xffffffffu, am, 2));
    am = fmaxf(am, __shfl_xor_sync(0xffffffffu, am, 4));
    float c6s, cM; uint32_t c2sb;
    mk_consts(am, c6s, cM, c2sb);

    size_t idx = (size_t)m * DOUT + o;
    const size_t ps = (size_t)NUM_T * DOUT;
    float4 r;
    r.x = qdq_fast(b4.x, c6s, cM, c2sb);
    r.y = qdq_fast(b4.y, c6s, cM, c2sb);
    r.z = qdq_fast(b4.z, c6s, cM, c2sb);
    r.w = qdq_fast(b4.w, c6s, cM, c2sb);
    #pragma unroll
    for (int s = 0; s < KS; s++) {
        float4 p = *reinterpret_cast<const float4*>(g_part + s * ps + idx);
        r.x += p.x; r.y += p.y; r.z += p.z; r.w += p.w;
    }
    *reinterpret_cast<float4*>(out + idx) = r;
}

// ---------------------------------------------------------------------------
extern "C" void kernel_launch(void* const* d_in, const int* in_sizes, int n_in,
                              void* d_out, int out_size) {
    const float* x = nullptr;
    const float* wgt = nullptr;
    const float* bias = nullptr;
    for (int i = 0; i < n_in; i++) {
        if (in_sizes[i] == NUM_T * DIN)     x    = (const float*)d_in[i];
        else if (in_sizes[i] == DOUT * DIN) wgt  = (const float*)d_in[i];
        else if (in_sizes[i] == DOUT)       bias = (const float*)d_in[i];
    }
    float* out = (float*)d_out;

    cudaFuncSetAttribute(fused_gemm_ws,
                         cudaFuncAttributeMaxDynamicSharedMemorySize, SMEM_TOTAL);

    qdq_x_kernel<<<NUM_T * DIN / 4 / 128, 128>>>(x);
    fused_gemm_ws<<<dim3(DOUT / NT, KS), 384, SMEM_TOTAL>>>(wgt);
    reduce_bias_kernel<<<(NUM_T * DOUT / 4) / 256, 256>>>(bias, out);
    (void)out_size;
}

// round 9
// speedup vs baseline: 1.1566x; 1.1566x over previous
#include <cuda_runtime.h>
#include <cuda_fp16.h>
#include <cstdint>

#define NUM_T 64
#define DIN   4096
#define DOUT  11008
#define KS    4
#define KPER  (DIN / KS)     // 1024
#define KC    64
#define NCHUNK (KPER / KC)   // 16
#define NT    64
#define SSTRIDE 72           // +8 half pad: row stride 144B, conflict-free ldmatrix
#define STAGE_BYTES (NUM_T * SSTRIDE * 2)   // 9216: one stage of Xs (or Ws)

// Scratch (allocation-free rule: __device__ globals)
__device__ __align__(256) __half g_xq[NUM_T * DIN];
__device__ __align__(256) float  g_part[KS * NUM_T * DOUT];   // 11.27 MB

// ---------------------------------------------------------------------------
// MXFP4 block constants from amax (integer bit-pattern construction)
// ---------------------------------------------------------------------------
__device__ __forceinline__ void mk_consts(float amax, float& c6s, float& cM,
                                          uint32_t& c2s_bits) {
    if (!(amax > 0.0f)) amax = 1.0f;
    int e  = ((__float_as_int(amax) >> 23) & 0xFF) - 127;
    int se = min(max(e - 2, -127), 127);
    c6s = __int_as_float(((se + 129) << 23) | 0x400000);   // 6 * 2^se
    cM  = __int_as_float((se + 149) << 23);                // 2^(se+22) magic
    c2s_bits = (uint32_t)((se + 128) << 23);               // bits of 2^(se+1)
}

// E2M1 qdq in the t-domain. Exactly matches reference (clip 6*scale, RNE on
// E2M1 grid incl. 0.5*scale subnormal step). rel_err 0.0 proven.
__device__ __forceinline__ float qdq_fast(float t, float c6s, float cM,
                                          uint32_t c2s_bits) {
    float a = fminf(fabsf(t), c6s);
    uint32_t u = __float_as_uint(a);
    uint32_t r1 = (u + 0x1FFFFFu + ((u >> 22) & 1u)) & 0xFFC00000u;
    float q2 = __fadd_rn(__fadd_rn(a, cM), -cM);
    uint32_t q = (u < c2s_bits) ? __float_as_uint(q2) : r1;
    return __uint_as_float(q | (__float_as_uint(t) & 0x80000000u));
}

// ---------------------------------------------------------------------------
// x quant-dequant -> f16 (one MXFP block = 8 lanes x float4)
// ---------------------------------------------------------------------------
__global__ void qdq_x_kernel(const float* __restrict__ in) {
    int gtid = blockIdx.x * blockDim.x + threadIdx.x;
    int warp = gtid >> 5;
    int lane = threadIdx.x & 31;
    long base = (long)warp * 128 + (long)lane * 4;
    if (base >= NUM_T * DIN) return;
    float4 v = *reinterpret_cast<const float4*>(in + base);
    float am = fmaxf(fmaxf(fabsf(v.x), fabsf(v.y)), fmaxf(fabsf(v.z), fabsf(v.w)));
    am = fmaxf(am, __shfl_xor_sync(0xffffffffu, am, 1));
    am = fmaxf(am, __shfl_xor_sync(0xffffffffu, am, 2));
    am = fmaxf(am, __shfl_xor_sync(0xffffffffu, am, 4));
    float c6s, cM; uint32_t c2sb;
    mk_consts(am, c6s, cM, c2sb);
    __half2 h0 = __floats2half2_rn(qdq_fast(v.x, c6s, cM, c2sb),
                                   qdq_fast(v.y, c6s, cM, c2sb));
    __half2 h1 = __floats2half2_rn(qdq_fast(v.z, c6s, cM, c2sb),
                                   qdq_fast(v.w, c6s, cM, c2sb));
    uint2 st;
    st.x = *reinterpret_cast<uint32_t*>(&h0);
    st.y = *reinterpret_cast<uint32_t*>(&h1);
    *reinterpret_cast<uint2*>(&g_xq[base]) = st;
}

// ---------------------------------------------------------------------------
// Fused GEMM, double-buffered, 512 threads: each thread quantizes only 8 W
// floats per chunk; 16 MMA warps (4M x 4N, 16x16 tiles each). 8 warps/SMSP.
// ---------------------------------------------------------------------------
#define LDMATRIX_X4(r0, r1, r2, r3, addr)                                        \
    asm volatile("ldmatrix.sync.aligned.m8n8.x4.shared.b16 {%0,%1,%2,%3}, [%4];" \
                 : "=r"(r0), "=r"(r1), "=r"(r2), "=r"(r3) : "r"(addr))

#define MMA16816(c, a0, a1, a2, a3, b0, b1)                                   \
    asm volatile("mma.sync.aligned.m16n8k16.row.col.f32.f16.f16.f32 "         \
                 "{%0,%1,%2,%3}, {%4,%5,%6,%7}, {%8,%9}, {%0,%1,%2,%3};"      \
                 : "+f"(c[0]), "+f"(c[1]), "+f"(c[2]), "+f"(c[3])             \
                 : "r"(a0), "r"(a1), "r"(a2), "r"(a3), "r"(b0), "r"(b1))

__global__ __launch_bounds__(512, 2) void fused_gemm_kernel(const float* __restrict__ W) {
    __shared__ __half Xs[2][NUM_T][SSTRIDE];
    __shared__ __half Ws[2][NT][SSTRIDE];

    int tid  = threadIdx.x;
    int w    = tid >> 5;
    int lane = tid & 31;
    int nbase = blockIdx.x * NT;
    int kbase = blockIdx.y * KPER;
    int mrow  = (w >> 2) * 16;     // warp M row   (4 M-groups)
    int ncol  = (w & 3) * 16;      // warp N col   (4 N-groups)

    float acc[2][4];
    #pragma unroll
    for (int i = 0; i < 2; i++)
        #pragma unroll
        for (int j = 0; j < 4; j++) acc[i][j] = 0.0f;

    int q = lane >> 3, li = lane & 7;
    uint32_t a_base0 = (uint32_t)__cvta_generic_to_shared(
        &Xs[0][mrow + (q & 1) * 8 + li][(q >> 1) * 8]);
    uint32_t b_base0 = (uint32_t)__cvta_generic_to_shared(
        &Ws[0][ncol + (q >> 1) * 8 + li][(q & 1) * 8]);

    // W load map: 8 threads per row, 8 consecutive floats (2 float4) each
    int wrow = tid >> 3;
    int wk   = (tid & 7) << 3;
    const float* wp = W + (size_t)(nbase + wrow) * DIN + kbase + wk;
    // X: same (row, col) map, 1 uint4 per thread
    const __half* xp = &g_xq[wrow * DIN + kbase + wk];

    float4 wv[2];
    uint4  xv;

    // quantize wv + stage X into buffer s
    auto stage = [&](int s) {
        *reinterpret_cast<uint4*>(&Xs[s][wrow][wk]) = xv;
        float am = fmaxf(fmaxf(fabsf(wv[0].x), fabsf(wv[0].y)),
                         fmaxf(fabsf(wv[0].z), fabsf(wv[0].w)));
        am = fmaxf(am, fmaxf(fmaxf(fabsf(wv[1].x), fabsf(wv[1].y)),
                             fmaxf(fabsf(wv[1].z), fabsf(wv[1].w))));
        am = fmaxf(am, __shfl_xor_sync(0xffffffffu, am, 1));
        am = fmaxf(am, __shfl_xor_sync(0xffffffffu, am, 2));  // 4 lanes = 32-block
        float c6s, cM; uint32_t c2sb;
        mk_consts(am, c6s, cM, c2sb);
        uint32_t qq[4];
        #pragma unroll
        for (int j = 0; j < 2; j++) {
            __half2 h0 = __floats2half2_rn(qdq_fast(wv[j].x, c6s, cM, c2sb),
                                           qdq_fast(wv[j].y, c6s, cM, c2sb));
            __half2 h1 = __floats2half2_rn(qdq_fast(wv[j].z, c6s, cM, c2sb),
                                           qdq_fast(wv[j].w, c6s, cM, c2sb));
            qq[2 * j]     = *reinterpret_cast<uint32_t*>(&h0);
            qq[2 * j + 1] = *reinterpret_cast<uint32_t*>(&h1);
        }
        *reinterpret_cast<uint4*>(&Ws[s][wrow][wk]) = make_uint4(qq[0], qq[1], qq[2], qq[3]);
    };

    // -------- prologue --------
    wv[0] = reinterpret_cast<const float4*>(wp)[0];
    wv[1] = reinterpret_cast<const float4*>(wp)[1];
    xv    = *reinterpret_cast<const uint4*>(xp);
    stage(0);
    wv[0] = reinterpret_cast<const float4*>(wp + KC)[0];
    wv[1] = reinterpret_cast<const float4*>(wp + KC)[1];
    xv    = *reinterpret_cast<const uint4*>(xp + KC);
    __syncthreads();

    // -------- main loop: one barrier per chunk --------
    #pragma unroll 1
    for (int c16 = 0; c16 < NCHUNK; c16++) {
        if (c16 + 1 < NCHUNK)
            stage((c16 + 1) & 1);
        if (c16 + 2 < NCHUNK) {
            int kc = (c16 + 2) * KC;
            wv[0] = reinterpret_cast<const float4*>(wp + kc)[0];
            wv[1] = reinterpret_cast<const float4*>(wp + kc)[1];
            xv    = *reinterpret_cast<const uint4*>(xp + kc);
        }
        // stage stride within Xs (and within Ws) is STAGE_BYTES = 9216
        uint32_t a_s = a_base0 + (c16 & 1) * STAGE_BYTES;
        uint32_t b_s = b_base0 + (c16 & 1) * STAGE_BYTES;
        #pragma unroll
        for (int ks = 0; ks < 4; ks++) {
            uint32_t a0, a1, a2, a3, b0, b1, b2, b3;
            LDMATRIX_X4(a0, a1, a2, a3, a_s + ks * 32);
            LDMATRIX_X4(b0, b1, b2, b3, b_s + ks * 32);
            MMA16816(acc[0], a0, a1, a2, a3, b0, b1);
            MMA16816(acc[1], a0, a1, a2, a3, b2, b3);
        }
        __syncthreads();
    }

    // epilogue: fp32 partials. Warp tile 16x16 at (mrow, nbase+ncol).
    float* pb = g_part + (size_t)blockIdx.y * NUM_T * DOUT;
    int tg = lane >> 2, tig = lane & 3;
    #pragma unroll
    for (int nf = 0; nf < 2; nf++) {
        int col = nbase + ncol + nf * 8 + tig * 2;
        int r0  = mrow + tg;
        *reinterpret_cast<float2*>(&pb[(size_t)r0 * DOUT + col]) =
            make_float2(acc[nf][0], acc[nf][1]);
        *reinterpret_cast<float2*>(&pb[(size_t)(r0 + 8) * DOUT + col]) =
            make_float2(acc[nf][2], acc[nf][3]);
    }
}

// ---------------------------------------------------------------------------
// Reduce K-splits + bias qdq. 1 thread = 1 float4 of output.
// ---------------------------------------------------------------------------
__global__ void reduce_bias_kernel(const float* __restrict__ bias, float* __restrict__ out) {
    int t  = blockIdx.x * blockDim.x + threadIdx.x;
    int m  = t / (DOUT / 4);
    int o  = (t % (DOUT / 4)) * 4;

    float4 b4 = *reinterpret_cast<const float4*>(bias + o);
    float am = fmaxf(fmaxf(fabsf(b4.x), fabsf(b4.y)), fmaxf(fabsf(b4.z), fabsf(b4.w)));
    am = fmaxf(am, __shfl_xor_sync(0xffffffffu, am, 1));
    am = fmaxf(am, __shfl_xor_sync(0xffffffffu, am, 2));
    am = fmaxf(am, __shfl_xor_sync(0xffffffffu, am, 4));
    float c6s, cM; uint32_t c2sb;
    mk_consts(am, c6s, cM, c2sb);

    size_t idx = (size_t)m * DOUT + o;
    const size_t ps = (size_t)NUM_T * DOUT;
    float4 r;
    r.x = qdq_fast(b4.x, c6s, cM, c2sb);
    r.y = qdq_fast(b4.y, c6s, cM, c2sb);
    r.z = qdq_fast(b4.z, c6s, cM, c2sb);
    r.w = qdq_fast(b4.w, c6s, cM, c2sb);
    #pragma unroll
    for (int s = 0; s < KS; s++) {
        float4 p = *reinterpret_cast<const float4*>(g_part + s * ps + idx);
        r.x += p.x; r.y += p.y; r.z += p.z; r.w += p.w;
    }
    *reinterpret_cast<float4*>(out + idx) = r;
}

// ---------------------------------------------------------------------------
extern "C" void kernel_launch(void* const* d_in, const int* in_sizes, int n_in,
                              void* d_out, int out_size) {
    const float* x = nullptr;
    const float* wgt = nullptr;
    const float* bias = nullptr;
    for (int i = 0; i < n_in; i++) {
        if (in_sizes[i] == NUM_T * DIN)     x    = (const float*)d_in[i];
        else if (in_sizes[i] == DOUT * DIN) wgt  = (const float*)d_in[i];
        else if (in_sizes[i] == DOUT)       bias = (const float*)d_in[i];
    }
    float* out = (float*)d_out;

    qdq_x_kernel<<<NUM_T * DIN / 4 / 128, 128>>>(x);
    fused_gemm_kernel<<<dim3(DOUT / NT, KS), 512>>>(wgt);
    reduce_bias_kernel<<<(NUM_T * DOUT / 4) / 256, 256>>>(bias, out);
    (void)out_size;
}